// round 1
// baseline (speedup 1.0000x reference)
#include <cuda_runtime.h>
#include <math.h>

// ---------------------------------------------------------------------------
// TemporalPromptGeneratorModel — fp32 baseline with algebraic reductions:
//  * attention == V (seq-len-1 softmax) -> fold Wv@Wo into W_eff (400x400)
//  * GRU h0==0 -> recurrent weights dead; GRU = elementwise on flat@K
//  * final cat GEMM = 3 accumulating GEMMs
// ---------------------------------------------------------------------------

#define BM 128
#define BN 128
#define BK 8
#define TM 8
#define TN 8

// ------------------------- scratch (device globals) ------------------------
__device__ float g_Weff[400 * 400];
__device__ float g_beff[400];
__device__ float g_attn[16383 * 400];
__device__ float g_flat[16384 * 1600];
__device__ float g_G[16384 * 5400];          // GRU preact scratch (reused f/b)
__device__ float g_x1[16384 * 3600];
__device__ float g_x3[16384 * 1800];
__device__ float g_x5[16384 * 1800];

// ------------------------------- SGEMM -------------------------------------
// C[M,N] = A[M,K] @ B[K,N]  (+bias) (+accumulate C) (+elu) | split-K atomic
// flags: bit0 accumulate into C, bit1 elu epilogue, bit2 split-K atomicAdd
__global__ __launch_bounds__(256, 2)
void sgemm_kernel(const float* __restrict__ A, const float* __restrict__ B,
                  float* __restrict__ C, const float* __restrict__ bias,
                  int M, int N, int K, int lda, int ldb, int ldc,
                  int flags, int kChunk)
{
    __shared__ float As[BK][BM];
    __shared__ float Bs[BK][BN];

    const int tid = threadIdx.x;
    const int tx = tid & 15;          // 0..15  (col micro)
    const int ty = tid >> 4;          // 0..15  (row micro)
    const int rowBase = blockIdx.y * BM;
    const int colBase = blockIdx.x * BN;

    const int kStart = blockIdx.z * kChunk;
    const int kEnd = min(kStart + kChunk, K);

    float acc[TM][TN];
#pragma unroll
    for (int i = 0; i < TM; i++)
#pragma unroll
        for (int j = 0; j < TN; j++) acc[i][j] = 0.f;

    // A tile: 128x8, one float4 per thread (along K). K is always %8==0.
    const int aRow = tid >> 1;
    const int aCol = (tid & 1) * 4;
    const int gARow = rowBase + aRow;
    // B tile: 8x128, one float4 per thread (along N). N is always %4==0.
    const int bRow = tid >> 5;
    const int bCol = (tid & 31) * 4;
    const int gBCol = colBase + bCol;

    for (int k0 = kStart; k0 < kEnd; k0 += BK) {
        float4 av = make_float4(0.f, 0.f, 0.f, 0.f);
        if (gARow < M)
            av = *reinterpret_cast<const float4*>(A + (size_t)gARow * lda + k0 + aCol);
        As[aCol + 0][aRow] = av.x;
        As[aCol + 1][aRow] = av.y;
        As[aCol + 2][aRow] = av.z;
        As[aCol + 3][aRow] = av.w;

        float4 bv = make_float4(0.f, 0.f, 0.f, 0.f);
        if (gBCol < N)
            bv = *reinterpret_cast<const float4*>(B + (size_t)(k0 + bRow) * ldb + gBCol);
        *reinterpret_cast<float4*>(&Bs[bRow][bCol]) = bv;
        __syncthreads();

#pragma unroll
        for (int kk = 0; kk < BK; kk++) {
            float4 a0 = *reinterpret_cast<const float4*>(&As[kk][ty * TM]);
            float4 a1 = *reinterpret_cast<const float4*>(&As[kk][ty * TM + 4]);
            float4 b0 = *reinterpret_cast<const float4*>(&Bs[kk][tx * TN]);
            float4 b1 = *reinterpret_cast<const float4*>(&Bs[kk][tx * TN + 4]);
            float a[TM] = {a0.x, a0.y, a0.z, a0.w, a1.x, a1.y, a1.z, a1.w};
            float b[TN] = {b0.x, b0.y, b0.z, b0.w, b1.x, b1.y, b1.z, b1.w};
#pragma unroll
            for (int i = 0; i < TM; i++)
#pragma unroll
                for (int j = 0; j < TN; j++)
                    acc[i][j] = fmaf(a[i], b[j], acc[i][j]);
        }
        __syncthreads();
    }

#pragma unroll
    for (int i = 0; i < TM; i++) {
        int row = rowBase + ty * TM + i;
        if (row >= M) continue;
#pragma unroll
        for (int j = 0; j < TN; j++) {
            int col = colBase + tx * TN + j;
            if (col >= N) continue;
            float v = acc[i][j];
            size_t off = (size_t)row * ldc + col;
            if (flags & 4) {
                atomicAdd(&C[off], v);
            } else {
                if (bias) v += bias[col];
                if (flags & 1) v += C[off];
                if (flags & 2) v = (v > 0.f) ? v : expm1f(v);
                C[off] = v;
            }
        }
    }
}

// ------------------------- small helper kernels ----------------------------
__global__ void zero_weff_kernel()
{
    int i = blockIdx.x * 256 + threadIdx.x;
    if (i < 400 * 400) g_Weff[i] = 0.f;
}

// b_eff[d] = bo[d] + sum_j bv[j] * Wo_flat[j, d]
__global__ void beff_kernel(const float* __restrict__ bv,
                            const float* __restrict__ Wo,
                            const float* __restrict__ bo)
{
    int d = blockIdx.x * 256 + threadIdx.x;
    if (d >= 400) return;
    float acc = bo[d];
    for (int j = 0; j < 6400; j++)
        acc = fmaf(bv[j], Wo[(size_t)j * 400 + d], acc);
    g_beff[d] = acc;
}

// flat[b, 0:1200] = x[b]; flat[0, 1200:1600] = x[0,2,:]
__global__ void build_flat_base(const float* __restrict__ x)
{
    int idx = blockIdx.x * 256 + threadIdx.x;
    const int total = 16384 * 1200;
    if (idx < total) {
        int b = idx / 1200, c = idx - b * 1200;
        g_flat[(size_t)b * 1600 + c] = x[idx];
    } else if (idx < total + 400) {
        int d = idx - total;
        g_flat[1200 + d] = x[800 + d];
    }
}

__device__ __forceinline__ float blockReduceSum(float v, float* sh)
{
#pragma unroll
    for (int o = 16; o > 0; o >>= 1) v += __shfl_xor_sync(0xffffffffu, v, o);
    int lane = threadIdx.x & 31, warp = threadIdx.x >> 5;
    if (lane == 0) sh[warp] = v;
    __syncthreads();
    if (warp == 0) {
        float r = (lane < 8) ? sh[lane] : 0.f;
#pragma unroll
        for (int o = 4; o > 0; o >>= 1) r += __shfl_xor_sync(0xffffffffu, r, o);
        if (lane == 0) sh[0] = r;
    }
    __syncthreads();
    float r = sh[0];
    __syncthreads();
    return r;
}

// Per encoder row b (0..16382): LN1(xe+attn) -> rank-2 FFN -> LN2 -> flat[b+1]
__global__ __launch_bounds__(256)
void frontend_kernel(const float* __restrict__ x,
                     const float* __restrict__ ln1g, const float* __restrict__ ln1b,
                     const float* __restrict__ w1,  const float* __restrict__ fb1,
                     const float* __restrict__ w2,  const float* __restrict__ fb2,
                     const float* __restrict__ ln2g, const float* __restrict__ ln2b)
{
    int b = blockIdx.x;
    const float* xe = x + (size_t)(b + 1) * 1200 + 800;
    const float* at = g_attn + (size_t)b * 400;
    __shared__ float red[32];
    int t = threadIdx.x;

    float sv[2], o1[2], s2v[2];
    int dIdx[2];
    int cnt = 0;
    float sum = 0.f, sq = 0.f;
    for (int d = t; d < 400; d += 256) {
        float v = xe[d] + at[d];
        sv[cnt] = v; dIdx[cnt] = d; cnt++;
        sum += v; sq += v * v;
    }
    sum = blockReduceSum(sum, red);
    sq  = blockReduceSum(sq, red);
    float mean = sum * (1.f / 400.f);
    float var  = sq * (1.f / 400.f) - mean * mean;
    float rstd = rsqrtf(var + 1e-6f);

    float t0 = 0.f, t1 = 0.f;
    for (int i = 0; i < cnt; i++) {
        int d = dIdx[i];
        float o = (sv[i] - mean) * rstd * ln1g[d] + ln1b[d];
        o1[i] = o;
        t0 = fmaf(o, w1[2 * d], t0);
        t1 = fmaf(o, w1[2 * d + 1], t1);
    }
    t0 = blockReduceSum(t0, red);
    t1 = blockReduceSum(t1, red);
    t0 = fmaxf(t0 + fb1[0], 0.f);
    t1 = fmaxf(t1 + fb1[1], 0.f);

    sum = 0.f; sq = 0.f;
    for (int i = 0; i < cnt; i++) {
        int d = dIdx[i];
        float v = o1[i] + t0 * w2[d] + t1 * w2[400 + d] + fb2[d];
        s2v[i] = v; sum += v; sq += v * v;
    }
    sum = blockReduceSum(sum, red);
    sq  = blockReduceSum(sq, red);
    mean = sum * (1.f / 400.f);
    var  = sq * (1.f / 400.f) - mean * mean;
    rstd = rsqrtf(var + 1e-6f);

    float* dst = g_flat + (size_t)(b + 1) * 1600 + 1200;
    for (int i = 0; i < cnt; i++) {
        int d = dIdx[i];
        dst[d] = (s2v[i] - mean) * rstd * ln2g[d] + ln2b[d];
    }
}

// GRU elementwise (h0 == 0): h = (1 - sigmoid(xz+rz)) * elu(xh + sigmoid(xr+rr)*rh)
__global__ void gru_elem_kernel(const float* __restrict__ Brow1, int colOff)
{
    int idx = blockIdx.x * 256 + threadIdx.x;
    if (idx >= 16384 * 1800) return;
    int b = idx / 1800, j = idx - b * 1800;
    const float* g = g_G + (size_t)b * 5400;
    float z = 1.f / (1.f + expf(-(g[j] + Brow1[j])));
    float r = 1.f / (1.f + expf(-(g[1800 + j] + Brow1[1800 + j])));
    float hv = g[3600 + j] + r * Brow1[3600 + j];
    float hh = (hv > 0.f) ? hv : expm1f(hv);
    g_x1[(size_t)b * 3600 + colOff + j] = (1.f - z) * hh;
}

// ------------------------------- host side ---------------------------------
static void launch_sgemm(const float* A, const float* B, float* C, const float* bias,
                         int M, int N, int K, int lda, int ldb, int ldc,
                         int flags, int splitK)
{
    dim3 grid((N + BN - 1) / BN, (M + BM - 1) / BM, splitK);
    int kChunk = (splitK > 1) ? (((K / splitK) + BK - 1) / BK) * BK : K;
    sgemm_kernel<<<grid, 256>>>(A, B, C, bias, M, N, K, lda, ldb, ldc, flags, kChunk);
}

extern "C" void kernel_launch(void* const* d_in, const int* in_sizes, int n_in,
                              void* d_out, int out_size)
{
    (void)n_in; (void)out_size;
    const float* x  = (const float*)d_in[0];
    const float* Wv = (const float*)d_in[5];
    const float* bv = (const float*)d_in[6];
    const float* Wo = (const float*)d_in[7];
    const float* bo = (const float*)d_in[8];

    // Input-order disambiguation: signature order has ln1_b (400 elems) at idx 10,
    // setup_inputs dict order has ffn_w1 (800 elems) there.
    bool sigOrder = (in_sizes[10] == 400);
    const float *ln1g, *ln1b, *w1, *fb1, *w2, *fb2, *ln2g, *ln2b;
    const float *gfk, *gfb, *gbk, *gbb, *d2w, *d2b, *d4w, *d4b, *ow, *ob;
    if (sigOrder) {
        ln1g = (const float*)d_in[9];  ln1b = (const float*)d_in[10];
        w1   = (const float*)d_in[11]; fb1  = (const float*)d_in[12];
        w2   = (const float*)d_in[13]; fb2  = (const float*)d_in[14];
        ln2g = (const float*)d_in[15]; ln2b = (const float*)d_in[16];
        gfk  = (const float*)d_in[17]; gfb  = (const float*)d_in[19];
        gbk  = (const float*)d_in[20]; gbb  = (const float*)d_in[22];
        d2w  = (const float*)d_in[23]; d2b  = (const float*)d_in[24];
        d4w  = (const float*)d_in[25]; d4b  = (const float*)d_in[26];
        ow   = (const float*)d_in[27]; ob   = (const float*)d_in[28];
    } else {
        ln1b = (const float*)d_in[9];
        w1   = (const float*)d_in[10]; fb1  = (const float*)d_in[11];
        w2   = (const float*)d_in[12]; fb2  = (const float*)d_in[13];
        ln2b = (const float*)d_in[14];
        gfk  = (const float*)d_in[15]; gfb  = (const float*)d_in[17];
        gbk  = (const float*)d_in[18]; gbb  = (const float*)d_in[20];
        d2w  = (const float*)d_in[21]; d2b  = (const float*)d_in[22];
        d4w  = (const float*)d_in[23]; d4b  = (const float*)d_in[24];
        ow   = (const float*)d_in[25]; ob   = (const float*)d_in[26];
        ln1g = (const float*)d_in[27]; ln2g = (const float*)d_in[28];
    }

    float *pWeff, *pattn, *pflat, *pG, *px1, *px3, *px5;
    cudaGetSymbolAddress((void**)&pWeff, g_Weff);
    cudaGetSymbolAddress((void**)&pattn, g_attn);
    cudaGetSymbolAddress((void**)&pflat, g_flat);
    cudaGetSymbolAddress((void**)&pG,    g_G);
    cudaGetSymbolAddress((void**)&px1,   g_x1);
    cudaGetSymbolAddress((void**)&px3,   g_x3);
    cudaGetSymbolAddress((void**)&px5,   g_x5);
    float* pbeff;
    cudaGetSymbolAddress((void**)&pbeff, g_beff);

    float* out = (float*)d_out;

    // 1) W_eff = Wv_flat(400x6400) @ Wo_flat(6400x400)  (split-K atomic)
    zero_weff_kernel<<<(400 * 400 + 255) / 256, 256>>>();
    launch_sgemm(Wv, Wo, pWeff, nullptr, 400, 400, 6400, 6400, 400, 400, /*flags*/4, /*splitK*/8);
    // 2) b_eff = bv @ Wo_flat + bo
    beff_kernel<<<2, 256>>>(bv, Wo, bo);
    // 3) attn = xe @ W_eff + b_eff   (xe: rows 1..16383, timestep 2 -> offset 2000, lda=1200)
    launch_sgemm(x + 2000, pWeff, pattn, pbeff, 16383, 400, 400, 1200, 400, 400, 0, 1);
    // 4) flat base = x (and row0 output)
    build_flat_base<<<(16384 * 1200 + 400 + 255) / 256, 256>>>(x);
    // 5) encoder frontend -> flat[:,1200:1600]
    frontend_kernel<<<16383, 256>>>(x, ln1g, ln1b, w1, fb1, w2, fb2, ln2g, ln2b);
    // 6) forward GRU: G = flat @ gru_fk + gru_fb[0];  x1[:, :1800]
    launch_sgemm(pflat, gfk, pG, gfb, 16384, 5400, 1600, 1600, 5400, 5400, 0, 1);
    gru_elem_kernel<<<(16384 * 1800 + 255) / 256, 256>>>(gfb + 5400, 0);
    // 7) backward GRU: G = flat @ gru_bk + gru_bb[0];  x1[:, 1800:]
    launch_sgemm(pflat, gbk, pG, gbb, 16384, 5400, 1600, 1600, 5400, 5400, 0, 1);
    gru_elem_kernel<<<(16384 * 1800 + 255) / 256, 256>>>(gbb + 5400, 1800);
    // 8) x3 = elu(x1 @ d2_w + d2_b)
    launch_sgemm(px1, d2w, px3, d2b, 16384, 1800, 3600, 3600, 1800, 1800, /*elu*/2, 1);
    // 9) x5 = elu(x3 @ d4_w + d4_b)
    launch_sgemm(px3, d4w, px5, d4b, 16384, 1800, 1800, 1800, 1800, 1800, /*elu*/2, 1);
    // 10) out = x1@W[0:3600] + x3@W[3600:5400] + x5@W[5400:7200] + out_b
    launch_sgemm(px1, ow,              out, ob,      16384, 140, 3600, 3600, 140, 140, 0, 1);
    launch_sgemm(px3, ow + 3600 * 140, out, nullptr, 16384, 140, 1800, 1800, 140, 140, /*acc*/1, 1);
    launch_sgemm(px5, ow + 5400 * 140, out, nullptr, 16384, 140, 1800, 1800, 140, 140, /*acc*/1, 1);
}